// round 2
// baseline (speedup 1.0000x reference)
#include <cuda_runtime.h>

#define NB 4
#define NC 512
#define CKQ 256
#define NW 64
#define NH 64
#define NN 4096   // H*W

// ---------------- scratch (device globals; no allocation allowed) -----------
__device__ float g_xbar[NB][NC][NW];      // mean over h of x
__device__ float g_x2d [NB][NC][NW];      // interpolated PE-injected row
__device__ float g_krow[NB][CKQ][NW];     // Wk @ x2d + bk
__device__ float g_vbar[NB][NC][NW];      // Wv @ xbar + bv
__device__ float g_M   [NB][NC][NW];      // Wq^T @ krow
__device__ float g_dw  [NB][NW];          // bq . krow
__device__ float g_At  [NB][NW][NN];      // softmax attn, w-major
__device__ float g_part[4][NB][NC][NW];   // split-K partials (deterministic)

// ---------------- K1: xbar[b][c][w] = mean_h x ------------------------------
__global__ void k_xbar(const float* __restrict__ x) {
  int c = blockIdx.x, b = blockIdx.y;
  int tid = threadIdx.x;
  int w = tid & 63, hq = tid >> 6;                 // 256 threads
  const float* xp = x + ((size_t)(b * NC + c)) * NH * NW;
  float s = 0.f;
  #pragma unroll 4
  for (int h = hq; h < NH; h += 4) s += xp[h * NW + w];
  __shared__ float sm[4][64];
  sm[hq][w] = s;
  __syncthreads();
  if (hq == 0)
    g_xbar[b][c][w] = (sm[0][w] + sm[1][w] + sm[2][w] + sm[3][w]) * (1.0f / NH);
}

// ---------------- K2: x1d + PE, interpolate back to W -----------------------
__global__ void k_x2d(const int* __restrict__ pos, const float* __restrict__ pe) {
  int b = blockIdx.x;
  int c = threadIdx.x;                             // 512 threads
  __shared__ int pidx[16];
  if (c < 16) pidx[c] = pos[b * NN + 4 * c] >> 3;  // pos[b][0][4*wp] // 8
  __syncthreads();
  float x1[16];
  #pragma unroll
  for (int wp = 0; wp < 16; wp++) {
    const float* xb = &g_xbar[b][c][4 * wp];
    x1[wp] = 0.25f * (xb[0] + xb[1] + xb[2] + xb[3]) + pe[pidx[wp] * NC + c];
  }
  #pragma unroll
  for (int w = 0; w < NW; w++) {
    float src = (w * 15.0f) / 63.0f;               // same fp32 ops as reference
    int   i0  = (int)floorf(src);
    int   i1  = min(i0 + 1, 15);
    float t   = src - (float)i0;
    g_x2d[b][c][w] = x1[i0] * (1.0f - t) + x1[i1] * t;
  }
}

// ---------------- generic small GEMM: part[ks][b][r][w] = sum_k Aeff(k,r)*X[b][k][w]
// TRANS=false: Aeff(k,r) = A[r*lda + k]   (weight @ activation)
// TRANS=true : Aeff(k,r) = A[k*lda + r]   (weight^T @ activation)
template <bool TRANS>
__global__ void k_gemm_part(const float* __restrict__ A, int lda,
                            const float* __restrict__ X,
                            float* __restrict__ part, int O, int Ktot) {
  int b = blockIdx.y, ks = blockIdx.z;
  int r0 = blockIdx.x * 64;
  int klen = Ktot >> 2;
  int c0base = ks * klen;
  __shared__ float As[16][68];
  __shared__ float Xs[16][68];
  int tid = threadIdx.x, ty = tid >> 4, tx = tid & 15;
  float acc[4][4] = {};
  const float* Xb = X + (size_t)b * Ktot * NW;
  for (int c0 = c0base; c0 < c0base + klen; c0 += 16) {
    if (TRANS) {
      int kk = tid >> 4, r4 = (tid & 15) * 4;
      *(float4*)&As[kk][r4] = *(const float4*)(A + (size_t)(c0 + kk) * lda + r0 + r4);
    } else {
      int rr = tid >> 2, k4 = (tid & 3) * 4;
      float4 v = *(const float4*)(A + (size_t)(r0 + rr) * lda + c0 + k4);
      As[k4 + 0][rr] = v.x; As[k4 + 1][rr] = v.y;
      As[k4 + 2][rr] = v.z; As[k4 + 3][rr] = v.w;
    }
    {
      int kk = tid >> 4, w4 = (tid & 15) * 4;
      *(float4*)&Xs[kk][w4] = *(const float4*)(Xb + (c0 + kk) * NW + w4);
    }
    __syncthreads();
    #pragma unroll
    for (int kk = 0; kk < 16; kk++) {
      float av[4], bv[4];
      *(float4*)av = *(float4*)&As[kk][ty * 4];
      *(float4*)bv = *(float4*)&Xs[kk][tx * 4];
      #pragma unroll
      for (int i = 0; i < 4; i++)
        #pragma unroll
        for (int j = 0; j < 4; j++)
          acc[i][j] = fmaf(av[i], bv[j], acc[i][j]);
    }
    __syncthreads();
  }
  float* pp = part + (((size_t)ks * NB + b) * O + r0) * NW;
  #pragma unroll
  for (int i = 0; i < 4; i++)
    *(float4*)&pp[(ty * 4 + i) * NW + tx * 4] = *(float4*)acc[i];
}

// ---------------- reduce 4 split-K partials + bias --------------------------
__global__ void k_reduce(const float* __restrict__ part, float* __restrict__ dst,
                         const float* __restrict__ bias, int O) {
  int idx = blockIdx.x * 256 + threadIdx.x;
  int total = NB * O * NW;
  if (idx >= total) return;
  int r = (idx >> 6) % O;
  float s = bias ? bias[r] : 0.0f;
  #pragma unroll
  for (int ks = 0; ks < 4; ks++) s += part[(size_t)ks * total + idx];
  dst[idx] = s;
}

// ---------------- dw[b][w] = bq . krow[b][:,w] -------------------------------
__global__ void k_dw(const float* __restrict__ bq) {
  int b = blockIdx.x, w = threadIdx.x;
  float s = 0.f;
  for (int o = 0; o < CKQ; o++) s += bq[o] * g_krow[b][o][w];
  g_dw[b][w] = s;
}

// ---------------- K4a: E = x^T M + dw, softmax over w, write A^T ------------
__global__ void k_attn(const float* __restrict__ x) {
  int b = blockIdx.y;
  int n0 = blockIdx.x * 64;
  __shared__ float As[16][68];
  __shared__ float Bs[16][68];
  __shared__ float Es[64][68];
  int tid = threadIdx.x, ty = tid >> 4, tx = tid & 15;
  float acc[4][4] = {};
  const float* xb = x + (size_t)b * NC * NN + n0;
  for (int c0 = 0; c0 < NC; c0 += 16) {
    int kk = tid >> 4, q4 = (tid & 15) * 4;
    *(float4*)&As[kk][q4] = *(const float4*)(xb + (size_t)(c0 + kk) * NN + q4);
    *(float4*)&Bs[kk][q4] = *(const float4*)(&g_M[b][c0 + kk][q4]);
    __syncthreads();
    #pragma unroll
    for (int kk2 = 0; kk2 < 16; kk2++) {
      float av[4], bv[4];
      *(float4*)av = *(float4*)&As[kk2][ty * 4];
      *(float4*)bv = *(float4*)&Bs[kk2][tx * 4];
      #pragma unroll
      for (int i = 0; i < 4; i++)
        #pragma unroll
        for (int j = 0; j < 4; j++)
          acc[i][j] = fmaf(av[i], bv[j], acc[i][j]);
    }
    __syncthreads();
  }
  #pragma unroll
  for (int i = 0; i < 4; i++)
    #pragma unroll
    for (int j = 0; j < 4; j++)
      Es[ty * 4 + i][tx * 4 + j] = acc[i][j] + g_dw[b][tx * 4 + j];
  __syncthreads();

  // softmax over w per row n: 4 threads per row
  int row = tid >> 2, q = tid & 3;
  float mx = -1e30f;
  for (int w = q; w < NW; w += 4) mx = fmaxf(mx, Es[row][w]);
  mx = fmaxf(mx, __shfl_xor_sync(0xffffffffu, mx, 1));
  mx = fmaxf(mx, __shfl_xor_sync(0xffffffffu, mx, 2));
  float s = 0.f;
  for (int w = q; w < NW; w += 4) {
    float e = __expf(Es[row][w] - mx);
    Es[row][w] = e;
    s += e;
  }
  s += __shfl_xor_sync(0xffffffffu, s, 1);
  s += __shfl_xor_sync(0xffffffffu, s, 2);
  float inv = 1.0f / s;
  for (int w = q; w < NW; w += 4) Es[row][w] *= inv;
  __syncthreads();

  // coalesced transposed store: g_At[b][w][n]
  for (int e = tid; e < 64 * 64; e += 256) {
    int w = e >> 6, nn = e & 63;
    g_At[b][w][n0 + nn] = Es[nn][w];
  }
}

// ---------------- K4b: out = gamma * (vbar @ A^T) + x -----------------------
__global__ void k_out(const float* __restrict__ x, const float* __restrict__ gamma,
                      float* __restrict__ out) {
  int b = blockIdx.z, c0 = blockIdx.y * 64, n0 = blockIdx.x * 64;
  __shared__ float Vs[64][68];   // [c][w]
  __shared__ float Aw[64][68];   // [w][n]
  int tid = threadIdx.x, ty = tid >> 4, tx = tid & 15;
  {
    int base = tid >> 4, q4 = (tid & 15) * 4;
    #pragma unroll
    for (int r = 0; r < 4; r++) {
      int rr = base + r * 16;
      *(float4*)&Vs[rr][q4] = *(const float4*)(&g_vbar[b][c0 + rr][q4]);
      *(float4*)&Aw[rr][q4] = *(const float4*)(&g_At[b][rr][n0 + q4]);
    }
  }
  __syncthreads();
  float acc[4][4] = {};
  #pragma unroll 4
  for (int w = 0; w < NW; w++) {
    float av[4], bv[4];
    #pragma unroll
    for (int i = 0; i < 4; i++) av[i] = Vs[ty * 4 + i][w];
    *(float4*)bv = *(float4*)&Aw[w][tx * 4];
    #pragma unroll
    for (int i = 0; i < 4; i++)
      #pragma unroll
      for (int j = 0; j < 4; j++)
        acc[i][j] = fmaf(av[i], bv[j], acc[i][j]);
  }
  float g = gamma[0];
  #pragma unroll
  for (int i = 0; i < 4; i++) {
    int c = c0 + ty * 4 + i;
    size_t off = (size_t)(b * NC + c) * NN + n0 + tx * 4;
    float4 xv = *(const float4*)(x + off);
    float4 o;
    o.x = fmaf(g, acc[i][0], xv.x);
    o.y = fmaf(g, acc[i][1], xv.y);
    o.z = fmaf(g, acc[i][2], xv.z);
    o.w = fmaf(g, acc[i][3], xv.w);
    *(float4*)(out + off) = o;
  }
}

// ---------------- launch ----------------------------------------------------
extern "C" void kernel_launch(void* const* d_in, const int* in_sizes, int n_in,
                              void* d_out, int out_size) {
  const float* x     = (const float*)d_in[0];
  const float* Wq    = (const float*)d_in[1];
  const float* bq    = (const float*)d_in[2];
  const float* Wk    = (const float*)d_in[3];
  const float* bk    = (const float*)d_in[4];
  const float* Wv    = (const float*)d_in[5];
  const float* bv    = (const float*)d_in[6];
  const float* gamma = (const float*)d_in[7];
  const float* pe    = (const float*)d_in[8];
  const int*   pos   = (const int*)  d_in[9];
  float* out = (float*)d_out;

  void *p_x2d, *p_xbar, *p_krow, *p_vbar, *p_M, *p_part;
  cudaGetSymbolAddress(&p_x2d,  g_x2d);
  cudaGetSymbolAddress(&p_xbar, g_xbar);
  cudaGetSymbolAddress(&p_krow, g_krow);
  cudaGetSymbolAddress(&p_vbar, g_vbar);
  cudaGetSymbolAddress(&p_M,    g_M);
  cudaGetSymbolAddress(&p_part, g_part);

  k_xbar<<<dim3(NC, NB), 256>>>(x);
  k_x2d<<<NB, NC>>>(pos, pe);

  // krow = Wk @ x2d + bk   (O=256, K=512)
  k_gemm_part<false><<<dim3(CKQ / 64, NB, 4), 256>>>(Wk, NC, (const float*)p_x2d,
                                                     (float*)p_part, CKQ, NC);
  k_reduce<<<(NB * CKQ * NW + 255) / 256, 256>>>((const float*)p_part,
                                                 (float*)p_krow, bk, CKQ);
  // vbar = Wv @ xbar + bv  (O=512, K=512)
  k_gemm_part<false><<<dim3(NC / 64, NB, 4), 256>>>(Wv, NC, (const float*)p_xbar,
                                                    (float*)p_part, NC, NC);
  k_reduce<<<(NB * NC * NW + 255) / 256, 256>>>((const float*)p_part,
                                                (float*)p_vbar, bv, NC);
  // M = Wq^T @ krow        (O=512 rows=c, K=256)
  k_gemm_part<true><<<dim3(NC / 64, NB, 4), 256>>>(Wq, NC, (const float*)p_krow,
                                                   (float*)p_part, NC, CKQ);
  k_reduce<<<(NB * NC * NW + 255) / 256, 256>>>((const float*)p_part,
                                                (float*)p_M, nullptr, NC);
  k_dw<<<NB, NW>>>(bq);

  k_attn<<<dim3(NN / 64, NB), 256>>>(x);
  k_out<<<dim3(NN / 64, NC / 64, NB), 256>>>(x, gamma, out);
}